// round 7
// baseline (speedup 1.0000x reference)
#include <cuda_runtime.h>
#include <math.h>

// Problem constants (fixed shapes per reference)
#define NN 50000
#define EE 800000
#define DD 256
#define CC 2
#define ETOT (EE + NN)   // edges + self loops = 850000
#define SLOPE 0.2f

// ---------------- scratch (__device__ globals; device-code-only references) --
__device__ float g_hA[(size_t)NN * DD];   // GEMM output h (per layer)
__device__ float g_hB[(size_t)NN * DD];   // aggregated/relu'd layer output
__device__ float g_es[NN];
__device__ float g_ed[NN];
__device__ int   g_deg[NN];
__device__ int   g_off[NN + 1];
__device__ int   g_cursor[NN];
__device__ int   g_csr_src[ETOT];
__device__ float g_ex[ETOT];
__device__ int   g_is64;                  // edge_index dtype flag (device-detected)

// ---------------- edge dtype probe ------------------------------------------
// If edge_index is int64 (little-endian, values < 2^31), every odd int32 word
// is the zero high-half. If int32, odd words are random node ids. 64 samples
// make misclassification probability ~(1/N)^64 ~ 0.
__global__ void k_detect(const int* __restrict__ ei) {
    int all0 = 1;
#pragma unroll
    for (int i = 1; i < 128; i += 2) all0 &= (ei[i] == 0);
    g_is64 = all0;
}

__device__ __forceinline__ int edge_src(const int* __restrict__ ei, int i) {
    return g_is64 ? ei[2 * i] : ei[i];
}
__device__ __forceinline__ int edge_dst(const int* __restrict__ ei, int i) {
    return g_is64 ? ei[2 * EE + 2 * i] : ei[EE + i];
}

// ---------------- CSR build --------------------------------------------------
__global__ void k_init_deg() {
    int i = blockIdx.x * blockDim.x + threadIdx.x;
    if (i < NN) g_deg[i] = 1;   // self loop counts
}

__global__ void k_hist(const int* __restrict__ ei) {
    int i = blockIdx.x * blockDim.x + threadIdx.x;
    if (i < EE) {
        int d = edge_dst(ei, i);
        if ((unsigned)d < NN) atomicAdd(&g_deg[d], 1);
    }
}

// single-block exclusive scan of g_deg -> g_off / g_cursor (N = 50000)
__global__ void k_scan() {
    __shared__ int part[1024];
    const int t = threadIdx.x;
    const int CH = (NN + 1023) / 1024;   // 49
    int b = t * CH;
    int e = min(b + CH, NN);
    int s = 0;
    for (int i = b; i < e; i++) s += g_deg[i];
    part[t] = s;
    __syncthreads();
    for (int off = 1; off < 1024; off <<= 1) {
        int v = (t >= off) ? part[t - off] : 0;
        __syncthreads();
        part[t] += v;
        __syncthreads();
    }
    int run = (t == 0) ? 0 : part[t - 1];
    for (int i = b; i < e; i++) {
        g_off[i] = run;
        g_cursor[i] = run;
        run += g_deg[i];
    }
    if (t == 1023) g_off[NN] = part[1023];
}

__global__ void k_fill(const int* __restrict__ ei) {
    int i = blockIdx.x * blockDim.x + threadIdx.x;
    if (i >= ETOT) return;
    int s, d;
    if (i < EE) {
        s = edge_src(ei, i);
        d = edge_dst(ei, i);
        if ((unsigned)s >= NN || (unsigned)d >= NN) return;  // defensive
    } else {
        s = d = i - EE;   // self loop
    }
    int pos = atomicAdd(&g_cursor[d], 1);
    if ((unsigned)pos < ETOT) g_csr_src[pos] = s;
}

// ---------------- SGEMM: g_hA = A @ W  (A = x, or g_hB if Aext == nullptr) ---
// 128x128 block tile, 8x8 thread micro-tile, BK=8, 256 threads.
__global__ void __launch_bounds__(256, 2)
k_gemm(const float* Aext, const float* __restrict__ B, int M) {
    const float* A = Aext ? Aext : (const float*)g_hB;
    float* Cout = g_hA;
    const int K = 256, NC = 256;
    __shared__ float As[8][128];
    __shared__ float Bs[8][128];
    const int tid = threadIdx.x;
    const int brow = blockIdx.x * 128;
    const int bcol = blockIdx.y * 128;
    const int trow = tid >> 4;          // 0..15
    const int tcol = tid & 15;          // 0..15
    const int a_row = tid >> 1;         // 2 threads per row, float4 each
    const int a_k   = (tid & 1) * 4;
    const int b_row = tid >> 5;         // 32 threads per row, float4 each
    const int b_col = (tid & 31) * 4;

    float acc[8][8];
#pragma unroll
    for (int i = 0; i < 8; i++)
#pragma unroll
        for (int j = 0; j < 8; j++) acc[i][j] = 0.f;

    for (int k0 = 0; k0 < K; k0 += 8) {
        int gr = brow + a_row;
        float4 av = make_float4(0.f, 0.f, 0.f, 0.f);
        if (gr < M) av = *(const float4*)&A[(size_t)gr * K + k0 + a_k];
        As[a_k + 0][a_row] = av.x;
        As[a_k + 1][a_row] = av.y;
        As[a_k + 2][a_row] = av.z;
        As[a_k + 3][a_row] = av.w;
        float4 bv = *(const float4*)&B[(size_t)(k0 + b_row) * NC + bcol + b_col];
        *(float4*)&Bs[b_row][b_col] = bv;
        __syncthreads();
#pragma unroll
        for (int kk = 0; kk < 8; kk++) {
            float ar[8], br[8];
            *(float4*)&ar[0] = *(const float4*)&As[kk][trow * 8 + 0];
            *(float4*)&ar[4] = *(const float4*)&As[kk][trow * 8 + 4];
            *(float4*)&br[0] = *(const float4*)&Bs[kk][tcol * 8 + 0];
            *(float4*)&br[4] = *(const float4*)&Bs[kk][tcol * 8 + 4];
#pragma unroll
            for (int i = 0; i < 8; i++)
#pragma unroll
                for (int j = 0; j < 8; j++)
                    acc[i][j] = fmaf(ar[i], br[j], acc[i][j]);
        }
        __syncthreads();
    }
#pragma unroll
    for (int i = 0; i < 8; i++) {
        int gr = brow + trow * 8 + i;
        if (gr < M) {
            *(float4*)&Cout[(size_t)gr * NC + bcol + tcol * 8 + 0] = *(float4*)&acc[i][0];
            *(float4*)&Cout[(size_t)gr * NC + bcol + tcol * 8 + 4] = *(float4*)&acc[i][4];
        }
    }
}

// ---------------- per-node attention dots: es = h.a_s, ed = h.a_d ------------
__global__ void k_attn(const float* __restrict__ a_s,
                       const float* __restrict__ a_d) {
    int warp = (blockIdx.x * blockDim.x + threadIdx.x) >> 5;
    int lane = threadIdx.x & 31;
    if (warp >= NN) return;
    const float* row = (const float*)g_hA + (size_t)warp * DD;
    float ss = 0.f, sd = 0.f;
#pragma unroll
    for (int j = 0; j < DD; j += 32) {
        float h = row[j + lane];
        ss = fmaf(h, a_s[j + lane], ss);
        sd = fmaf(h, a_d[j + lane], sd);
    }
#pragma unroll
    for (int o = 16; o; o >>= 1) {
        ss += __shfl_xor_sync(0xFFFFFFFFu, ss, o);
        sd += __shfl_xor_sync(0xFFFFFFFFu, sd, o);
    }
    if (lane == 0) { g_es[warp] = ss; g_ed[warp] = sd; }
}

// ---------------- aggregation: segment softmax + weighted gather, relu -------
// one 256-thread block per destination node; tid == feature dim in pass C.
__global__ void __launch_bounds__(256)
k_aggr(const float* __restrict__ bias) {
    const float* Hin = (const float*)g_hA;
    float* Hout = g_hB;
    const int node = blockIdx.x;
    const int tid = threadIdx.x;
    const int beg = g_off[node];
    const int end = g_off[node + 1];
    const float edv = g_ed[node];

    __shared__ float red[8];
    __shared__ float s_m, s_inv;
    __shared__ int   s_src[128];
    __shared__ float s_w[128];

    // pass A: segment max of leaky_relu(es[src]+ed[dst])
    float m = -1e30f;
    for (int j = beg + tid; j < end; j += 256) {
        float e = g_es[g_csr_src[j]] + edv;
        e = (e > 0.f) ? e : SLOPE * e;
        m = fmaxf(m, e);
    }
#pragma unroll
    for (int o = 16; o; o >>= 1) m = fmaxf(m, __shfl_xor_sync(0xFFFFFFFFu, m, o));
    if ((tid & 31) == 0) red[tid >> 5] = m;
    __syncthreads();
    if (tid < 8) {
        float v = red[tid];
#pragma unroll
        for (int o = 4; o; o >>= 1) v = fmaxf(v, __shfl_xor_sync(0xFFu, v, o));
        if (tid == 0) s_m = v;
    }
    __syncthreads();
    const float mm = s_m;

    // pass B: exp and denominator
    float den = 0.f;
    for (int j = beg + tid; j < end; j += 256) {
        float e = g_es[g_csr_src[j]] + edv;
        e = (e > 0.f) ? e : SLOPE * e;
        float ex = __expf(e - mm);
        g_ex[j] = ex;
        den += ex;
    }
#pragma unroll
    for (int o = 16; o; o >>= 1) den += __shfl_xor_sync(0xFFFFFFFFu, den, o);
    if ((tid & 31) == 0) red[tid >> 5] = den;
    __syncthreads();
    if (tid < 8) {
        float v = red[tid];
#pragma unroll
        for (int o = 4; o; o >>= 1) v += __shfl_xor_sync(0xFFu, v, o);
        if (tid == 0) s_inv = 1.f / v;
    }
    __syncthreads();
    const float inv = s_inv;

    // pass C: weighted gather of source features (tid == feature dim)
    float acc = 0.f;
    for (int base = beg; base < end; base += 128) {
        int n = min(128, end - base);
        __syncthreads();
        if (tid < n) {
            s_src[tid] = g_csr_src[base + tid];
            s_w[tid]   = g_ex[base + tid];
        }
        __syncthreads();
        for (int k = 0; k < n; k++)
            acc = fmaf(s_w[k], Hin[(size_t)s_src[k] * DD + tid], acc);
    }
    float out = fmaf(acc, inv, bias[tid]);
    out = fmaxf(out, 0.f);   // relu (both GAT layers are relu'd in reference)
    Hout[(size_t)node * DD + tid] = out;
}

// ---------------- classifier + log_softmax (H = g_hB) ------------------------
__global__ void k_cls(const float* __restrict__ Wc,
                      const float* __restrict__ bc, float* __restrict__ out) {
    int warp = (blockIdx.x * blockDim.x + threadIdx.x) >> 5;
    int lane = threadIdx.x & 31;
    if (warp >= NN) return;
    const float* row = (const float*)g_hB + (size_t)warp * DD;
    float l0 = 0.f, l1 = 0.f;
#pragma unroll
    for (int j = lane; j < DD; j += 32) {
        float h = row[j];
        l0 = fmaf(h, Wc[2 * j + 0], l0);
        l1 = fmaf(h, Wc[2 * j + 1], l1);
    }
#pragma unroll
    for (int o = 16; o; o >>= 1) {
        l0 += __shfl_xor_sync(0xFFFFFFFFu, l0, o);
        l1 += __shfl_xor_sync(0xFFFFFFFFu, l1, o);
    }
    if (lane == 0) {
        l0 += bc[0]; l1 += bc[1];
        float mx = fmaxf(l0, l1);
        float z0 = l0 - mx, z1 = l1 - mx;
        float lse = logf(expf(z0) + expf(z1));
        out[(size_t)warp * 2 + 0] = z0 - lse;
        out[(size_t)warp * 2 + 1] = z1 - lse;
    }
}

// ---------------- launch ------------------------------------------------------
extern "C" void kernel_launch(void* const* d_in, const int* in_sizes, int n_in,
                              void* d_out, int out_size) {
    const float* x   = (const float*)d_in[0];
    const int*   ei  = (const int*)d_in[1];    // int32 OR int64 (device-probed)
    const float* W1  = (const float*)d_in[2];
    const float* a1s = (const float*)d_in[3];
    const float* a1d = (const float*)d_in[4];
    const float* b1  = (const float*)d_in[5];
    const float* W2  = (const float*)d_in[6];
    const float* a2s = (const float*)d_in[7];
    const float* a2d = (const float*)d_in[8];
    const float* b2  = (const float*)d_in[9];
    const float* Wc  = (const float*)d_in[10];
    const float* bc  = (const float*)d_in[11];
    float*       out = (float*)d_out;

    // CSR build (every call; deterministic values up to fp sum order)
    k_detect<<<1, 1>>>(ei);
    k_init_deg<<<(NN + 255) / 256, 256>>>();
    k_hist<<<(EE + 255) / 256, 256>>>(ei);
    k_scan<<<1, 1024>>>();
    k_fill<<<(ETOT + 255) / 256, 256>>>(ei);

    dim3 ggrid((NN + 127) / 128, DD / 128);   // 391 x 2
    int attn_blocks = (NN * 32 + 255) / 256;  // warp per node

    // layer 1: g_hA = x @ W1 ; attn ; g_hB = relu(aggr(g_hA) + b1)
    k_gemm<<<ggrid, 256>>>(x, W1, NN);
    k_attn<<<attn_blocks, 256>>>(a1s, a1d);
    k_aggr<<<NN, 256>>>(b1);

    // layer 2: g_hA = g_hB @ W2 ; attn ; g_hB = relu(aggr(g_hA) + b2)
    k_gemm<<<ggrid, 256>>>(nullptr, W2, NN);
    k_attn<<<attn_blocks, 256>>>(a2s, a2d);
    k_aggr<<<NN, 256>>>(b2);

    // classifier + log_softmax
    k_cls<<<attn_blocks, 256>>>(Wc, bc, out);
}

// round 8
// speedup vs baseline: 1.1116x; 1.1116x over previous
#include <cuda_runtime.h>
#include <math.h>

// Problem constants (fixed shapes per reference)
#define NN 50000
#define EE 800000
#define DD 256
#define CC 2
#define ETOT (EE + NN)   // edges + self loops = 850000
#define SLOPE 0.2f
#define SCB 196          // ceil(NN / 256) scan blocks

// ---------------- scratch (__device__ globals; device-code-only references) --
__device__ float g_hA[(size_t)NN * DD];   // GEMM output h (per layer)
__device__ float g_hB[(size_t)NN * DD];   // layer-1 aggregated output
__device__ float g_es[NN];
__device__ float g_ed[NN];
__device__ int   g_deg[NN];
__device__ int   g_off[NN + 1];
__device__ int   g_cursor[NN];
__device__ int   g_csr_src[ETOT];
__device__ float g_ex[ETOT];
__device__ int   g_part[256];             // scan partials (SCB used)
__device__ int   g_is64;                  // edge_index dtype flag

// ---------------- edge dtype probe ------------------------------------------
__global__ void k_detect(const int* __restrict__ ei) {
    int all0 = 1;
#pragma unroll
    for (int i = 1; i < 128; i += 2) all0 &= (ei[i] == 0);
    g_is64 = all0;
}

__device__ __forceinline__ int edge_src(const int* __restrict__ ei, int i) {
    return g_is64 ? ei[2 * i] : ei[i];
}
__device__ __forceinline__ int edge_dst(const int* __restrict__ ei, int i) {
    return g_is64 ? ei[2 * EE + 2 * i] : ei[EE + i];
}

// ---------------- CSR build ---------------------------------------------------
__global__ void k_init_deg() {
    int i = blockIdx.x * blockDim.x + threadIdx.x;
    if (i < NN) g_deg[i] = 1;   // self loop
}

__global__ void k_zero_attn() {
    int i = blockIdx.x * blockDim.x + threadIdx.x;
    if (i < NN) { g_es[i] = 0.f; g_ed[i] = 0.f; }
}

__global__ void k_hist(const int* __restrict__ ei) {
    int i = blockIdx.x * blockDim.x + threadIdx.x;
    if (i < EE) {
        int d = edge_dst(ei, i);
        if ((unsigned)d < NN) atomicAdd(&g_deg[d], 1);
    }
}

// scan stage 1: per-block sums of g_deg (grid SCB, 256 thr)
__global__ void k_scan1() {
    __shared__ int red[8];
    int i = blockIdx.x * 256 + threadIdx.x;
    int v = (i < NN) ? g_deg[i] : 0;
    int s = v;
#pragma unroll
    for (int o = 16; o; o >>= 1) s += __shfl_xor_sync(0xFFFFFFFFu, s, o);
    if ((threadIdx.x & 31) == 0) red[threadIdx.x >> 5] = s;
    __syncthreads();
    if (threadIdx.x < 8) {
        int t = red[threadIdx.x];
#pragma unroll
        for (int o = 4; o; o >>= 1) t += __shfl_xor_sync(0xFFu, t, o);
        if (threadIdx.x == 0) g_part[blockIdx.x] = t;
    }
}

// scan stage 2: exclusive scan of SCB partials (1 block, 256 thr)
__global__ void k_scan2() {
    __shared__ int sm[256];
    int t = threadIdx.x;
    int v = (t < SCB) ? g_part[t] : 0;
    sm[t] = v;
    __syncthreads();
#pragma unroll
    for (int off = 1; off < 256; off <<= 1) {
        int u = (t >= off) ? sm[t - off] : 0;
        __syncthreads();
        sm[t] += u;
        __syncthreads();
    }
    if (t < SCB) g_part[t] = sm[t] - v;   // exclusive base per block
}

// scan stage 3: block-local exclusive scan + base (grid SCB, 256 thr)
__global__ void k_scan3() {
    __shared__ int sm[256];
    int t = threadIdx.x;
    int i = blockIdx.x * 256 + t;
    int v = (i < NN) ? g_deg[i] : 0;
    sm[t] = v;
    __syncthreads();
#pragma unroll
    for (int off = 1; off < 256; off <<= 1) {
        int u = (t >= off) ? sm[t - off] : 0;
        __syncthreads();
        sm[t] += u;
        __syncthreads();
    }
    int excl = sm[t] - v + g_part[blockIdx.x];
    if (i < NN) { g_off[i] = excl; g_cursor[i] = excl; }
    if (i == NN - 1) g_off[NN] = excl + v;
}

__global__ void k_fill(const int* __restrict__ ei) {
    int i = blockIdx.x * blockDim.x + threadIdx.x;
    if (i >= ETOT) return;
    int s, d;
    if (i < EE) {
        s = edge_src(ei, i);
        d = edge_dst(ei, i);
        if ((unsigned)s >= NN || (unsigned)d >= NN) return;  // defensive
    } else {
        s = d = i - EE;   // self loop
    }
    int pos = atomicAdd(&g_cursor[d], 1);
    if ((unsigned)pos < ETOT) g_csr_src[pos] = s;
}

// ---------------- SGEMM + fused attention dots --------------------------------
// g_hA = A @ W ; g_es += (A@W).a_s ; g_ed += (A@W).a_d
// 128x128 tile, 8x8 micro-tile, BK=8, 256 threads, double-buffered smem.
__global__ void __launch_bounds__(256, 2)
k_gemm(const float* Aext, const float* __restrict__ B, int M,
       const float* __restrict__ a_s, const float* __restrict__ a_d) {
    const float* A = Aext ? Aext : (const float*)g_hB;
    float* Cout = g_hA;
    const int K = 256, NC = 256;
    __shared__ float As[2][8][128];
    __shared__ float Bs[2][8][128];
    const int tid = threadIdx.x;
    const int brow = blockIdx.x * 128;
    const int bcol = blockIdx.y * 128;
    const int trow = tid >> 4;          // 0..15
    const int tcol = tid & 15;          // 0..15
    const int a_row = tid >> 1;         // 2 threads per row, float4 each
    const int a_k   = (tid & 1) * 4;
    const int b_row = tid >> 5;         // 32 threads per row, float4 each
    const int b_col = (tid & 31) * 4;

    float acc[8][8];
#pragma unroll
    for (int i = 0; i < 8; i++)
#pragma unroll
        for (int j = 0; j < 8; j++) acc[i][j] = 0.f;

    // prologue: stage tile k0=0 into buffer 0
    {
        int gr = brow + a_row;
        float4 av = make_float4(0.f, 0.f, 0.f, 0.f);
        if (gr < M) av = *(const float4*)&A[(size_t)gr * K + a_k];
        As[0][a_k + 0][a_row] = av.x;
        As[0][a_k + 1][a_row] = av.y;
        As[0][a_k + 2][a_row] = av.z;
        As[0][a_k + 3][a_row] = av.w;
        float4 bv = *(const float4*)&B[(size_t)b_row * NC + bcol + b_col];
        *(float4*)&Bs[0][b_row][b_col] = bv;
    }
    __syncthreads();

    int buf = 0;
    for (int k0 = 0; k0 < K; k0 += 8) {
        // issue next tile's global loads early (latency hidden by 512 FMAs)
        float4 av, bv;
        const bool more = (k0 + 8 < K);
        if (more) {
            int gr = brow + a_row;
            av = make_float4(0.f, 0.f, 0.f, 0.f);
            if (gr < M) av = *(const float4*)&A[(size_t)gr * K + k0 + 8 + a_k];
            bv = *(const float4*)&B[(size_t)(k0 + 8 + b_row) * NC + bcol + b_col];
        }
#pragma unroll
        for (int kk = 0; kk < 8; kk++) {
            float ar[8], br[8];
            *(float4*)&ar[0] = *(const float4*)&As[buf][kk][trow * 8 + 0];
            *(float4*)&ar[4] = *(const float4*)&As[buf][kk][trow * 8 + 4];
            *(float4*)&br[0] = *(const float4*)&Bs[buf][kk][tcol * 8 + 0];
            *(float4*)&br[4] = *(const float4*)&Bs[buf][kk][tcol * 8 + 4];
#pragma unroll
            for (int i = 0; i < 8; i++)
#pragma unroll
                for (int j = 0; j < 8; j++)
                    acc[i][j] = fmaf(ar[i], br[j], acc[i][j]);
        }
        if (more) {
            int nb = buf ^ 1;
            As[nb][a_k + 0][a_row] = av.x;
            As[nb][a_k + 1][a_row] = av.y;
            As[nb][a_k + 2][a_row] = av.z;
            As[nb][a_k + 3][a_row] = av.w;
            *(float4*)&Bs[nb][b_row][b_col] = bv;
            __syncthreads();
            buf = nb;
        }
    }

    // epilogue: store C and accumulate attention dots
    float asv[8], adv[8];
#pragma unroll
    for (int j = 0; j < 8; j++) {
        asv[j] = a_s[bcol + tcol * 8 + j];
        adv[j] = a_d[bcol + tcol * 8 + j];
    }
#pragma unroll
    for (int i = 0; i < 8; i++) {
        int gr = brow + trow * 8 + i;
        float ps = 0.f, pd = 0.f;
#pragma unroll
        for (int j = 0; j < 8; j++) {
            ps = fmaf(acc[i][j], asv[j], ps);
            pd = fmaf(acc[i][j], adv[j], pd);
        }
        // reduce across the 16 lanes sharing this row (contiguous lanes in warp)
#pragma unroll
        for (int o = 8; o; o >>= 1) {
            ps += __shfl_xor_sync(0xFFFFFFFFu, ps, o);
            pd += __shfl_xor_sync(0xFFFFFFFFu, pd, o);
        }
        if (gr < M) {
            *(float4*)&Cout[(size_t)gr * NC + bcol + tcol * 8 + 0] = *(float4*)&acc[i][0];
            *(float4*)&Cout[(size_t)gr * NC + bcol + tcol * 8 + 4] = *(float4*)&acc[i][4];
            if ((tid & 15) == 0) {
                atomicAdd(&g_es[gr], ps);
                atomicAdd(&g_ed[gr], pd);
            }
        }
    }
}

// ---------------- aggregation: segment softmax + weighted gather --------------
// one 256-thread block per dst node; tid == feature dim in pass C.
// If Wc != nullptr: fused classifier + log_softmax, writes out[node*2+..]
// instead of storing features.
__global__ void __launch_bounds__(256)
k_aggr(const float* __restrict__ bias,
       const float* __restrict__ Wc, const float* __restrict__ bc,
       float* __restrict__ cls_out) {
    const float* Hin = (const float*)g_hA;
    const int node = blockIdx.x;
    const int tid = threadIdx.x;
    const int beg = g_off[node];
    const int end = g_off[node + 1];
    const float edv = g_ed[node];

    __shared__ float red[8];
    __shared__ float s_m, s_inv;
    __shared__ int   s_src[128];
    __shared__ float s_w[128];

    // pass A: e = leaky_relu(es[src]+ed[dst]); store e; segment max
    float m = -1e30f;
    for (int j = beg + tid; j < end; j += 256) {
        float e = g_es[g_csr_src[j]] + edv;
        e = (e > 0.f) ? e : SLOPE * e;
        g_ex[j] = e;
        m = fmaxf(m, e);
    }
#pragma unroll
    for (int o = 16; o; o >>= 1) m = fmaxf(m, __shfl_xor_sync(0xFFFFFFFFu, m, o));
    if ((tid & 31) == 0) red[tid >> 5] = m;
    __syncthreads();
    if (tid < 8) {
        float v = red[tid];
#pragma unroll
        for (int o = 4; o; o >>= 1) v = fmaxf(v, __shfl_xor_sync(0xFFu, v, o));
        if (tid == 0) s_m = v;
    }
    __syncthreads();
    const float mm = s_m;

    // pass B: exp (reuse stored e, linear access) and denominator
    float den = 0.f;
    for (int j = beg + tid; j < end; j += 256) {
        float ex = __expf(g_ex[j] - mm);
        g_ex[j] = ex;
        den += ex;
    }
#pragma unroll
    for (int o = 16; o; o >>= 1) den += __shfl_xor_sync(0xFFFFFFFFu, den, o);
    if ((tid & 31) == 0) red[tid >> 5] = den;
    __syncthreads();
    if (tid < 8) {
        float v = red[tid];
#pragma unroll
        for (int o = 4; o; o >>= 1) v += __shfl_xor_sync(0xFFu, v, o);
        if (tid == 0) s_inv = 1.f / v;
    }
    __syncthreads();
    const float inv = s_inv;

    // pass C: weighted gather of source features (tid == feature dim)
    float acc = 0.f;
    for (int base = beg; base < end; base += 128) {
        int n = min(128, end - base);
        __syncthreads();
        if (tid < n) {
            s_src[tid] = g_csr_src[base + tid];
            s_w[tid]   = g_ex[base + tid];
        }
        __syncthreads();
        for (int k = 0; k < n; k++)
            acc = fmaf(s_w[k], Hin[(size_t)s_src[k] * DD + tid], acc);
    }
    float val = fmaf(acc, inv, bias[tid]);
    val = fmaxf(val, 0.f);   // relu

    if (Wc == nullptr) {
        g_hB[(size_t)node * DD + tid] = val;
        return;
    }

    // fused classifier + log_softmax
    float p0 = val * Wc[2 * tid + 0];
    float p1 = val * Wc[2 * tid + 1];
#pragma unroll
    for (int o = 16; o; o >>= 1) {
        p0 += __shfl_xor_sync(0xFFFFFFFFu, p0, o);
        p1 += __shfl_xor_sync(0xFFFFFFFFu, p1, o);
    }
    __syncthreads();
    if ((tid & 31) == 0) { red[tid >> 5] = p0; }
    __syncthreads();
    float l0 = 0.f, l1 = 0.f;
    if (tid < 8) l0 = red[tid];
    __syncthreads();
    if ((tid & 31) == 0) { red[tid >> 5] = p1; }
    __syncthreads();
    if (tid < 8) {
        l1 = red[tid];
#pragma unroll
        for (int o = 4; o; o >>= 1) {
            l0 += __shfl_xor_sync(0xFFu, l0, o);
            l1 += __shfl_xor_sync(0xFFu, l1, o);
        }
        if (tid == 0) {
            l0 += bc[0]; l1 += bc[1];
            float mx = fmaxf(l0, l1);
            float z0 = l0 - mx, z1 = l1 - mx;
            float lse = logf(expf(z0) + expf(z1));
            cls_out[(size_t)node * 2 + 0] = z0 - lse;
            cls_out[(size_t)node * 2 + 1] = z1 - lse;
        }
    }
}

// ---------------- launch --------------------------------------------------------
extern "C" void kernel_launch(void* const* d_in, const int* in_sizes, int n_in,
                              void* d_out, int out_size) {
    const float* x   = (const float*)d_in[0];
    const int*   ei  = (const int*)d_in[1];    // int32 OR int64 (device-probed)
    const float* W1  = (const float*)d_in[2];
    const float* a1s = (const float*)d_in[3];
    const float* a1d = (const float*)d_in[4];
    const float* b1  = (const float*)d_in[5];
    const float* W2  = (const float*)d_in[6];
    const float* a2s = (const float*)d_in[7];
    const float* a2d = (const float*)d_in[8];
    const float* b2  = (const float*)d_in[9];
    const float* Wc  = (const float*)d_in[10];
    const float* bc  = (const float*)d_in[11];
    float*       out = (float*)d_out;

    // CSR build
    k_detect<<<1, 1>>>(ei);
    k_init_deg<<<SCB, 256>>>();
    k_hist<<<(EE + 255) / 256, 256>>>(ei);
    k_scan1<<<SCB, 256>>>();
    k_scan2<<<1, 256>>>();
    k_scan3<<<SCB, 256>>>();
    k_fill<<<(ETOT + 255) / 256, 256>>>(ei);

    dim3 ggrid((NN + 127) / 128, DD / 128);   // 391 x 2

    // layer 1
    k_zero_attn<<<SCB, 256>>>();
    k_gemm<<<ggrid, 256>>>(x, W1, NN, a1s, a1d);
    k_aggr<<<NN, 256>>>(b1, nullptr, nullptr, nullptr);

    // layer 2 (+ fused classifier)
    k_zero_attn<<<SCB, 256>>>();
    k_gemm<<<ggrid, 256>>>(nullptr, W2, NN, a2s, a2d);
    k_aggr<<<NN, 256>>>(b2, Wc, bc, out);
}

// round 9
// speedup vs baseline: 1.1508x; 1.0352x over previous
#include <cuda_runtime.h>
#include <math.h>
#include <stdint.h>

// Problem constants (fixed shapes per reference)
#define NN 50000
#define EE 800000
#define DD 256
#define CC 2
#define ETOT (EE + NN)   // edges + self loops = 850000
#define SLOPE 0.2f
#define SCB 196          // ceil(NN / 256) scan blocks

// ---------------- scratch (__device__ globals; device-code-only references) --
__device__ float g_hA[(size_t)NN * DD];   // GEMM output h (per layer)
__device__ float g_hB[(size_t)NN * DD];   // layer-1 aggregated output
__device__ float g_es[NN];
__device__ float g_ed[NN];
__device__ int   g_deg[NN];
__device__ int   g_off[NN + 1];
__device__ int   g_cursor[NN];
__device__ int   g_csr_src[ETOT];
__device__ float g_ex[ETOT];
__device__ int   g_part[256];             // scan partials (SCB used)
__device__ int   g_is64;                  // edge_index dtype flag

// ---------------- edge dtype probe ------------------------------------------
__global__ void k_detect(const int* __restrict__ ei) {
    int all0 = 1;
#pragma unroll
    for (int i = 1; i < 128; i += 2) all0 &= (ei[i] == 0);
    g_is64 = all0;
}

__device__ __forceinline__ int edge_src(const int* __restrict__ ei, int i) {
    return g_is64 ? ei[2 * i] : ei[i];
}
__device__ __forceinline__ int edge_dst(const int* __restrict__ ei, int i) {
    return g_is64 ? ei[2 * EE + 2 * i] : ei[EE + i];
}

// ---------------- CSR build ---------------------------------------------------
__global__ void k_init_deg() {
    int i = blockIdx.x * blockDim.x + threadIdx.x;
    if (i < NN) g_deg[i] = 1;   // self loop
}

__global__ void k_zero_attn() {
    int i = blockIdx.x * blockDim.x + threadIdx.x;
    if (i < NN) { g_es[i] = 0.f; g_ed[i] = 0.f; }
}

__global__ void k_hist(const int* __restrict__ ei) {
    int i = blockIdx.x * blockDim.x + threadIdx.x;
    if (i < EE) {
        int d = edge_dst(ei, i);
        if ((unsigned)d < NN) atomicAdd(&g_deg[d], 1);
    }
}

__global__ void k_scan1() {
    __shared__ int red[8];
    int i = blockIdx.x * 256 + threadIdx.x;
    int v = (i < NN) ? g_deg[i] : 0;
    int s = v;
#pragma unroll
    for (int o = 16; o; o >>= 1) s += __shfl_xor_sync(0xFFFFFFFFu, s, o);
    if ((threadIdx.x & 31) == 0) red[threadIdx.x >> 5] = s;
    __syncthreads();
    if (threadIdx.x < 8) {
        int t = red[threadIdx.x];
#pragma unroll
        for (int o = 4; o; o >>= 1) t += __shfl_xor_sync(0xFFu, t, o);
        if (threadIdx.x == 0) g_part[blockIdx.x] = t;
    }
}

__global__ void k_scan2() {
    __shared__ int sm[256];
    int t = threadIdx.x;
    int v = (t < SCB) ? g_part[t] : 0;
    sm[t] = v;
    __syncthreads();
#pragma unroll
    for (int off = 1; off < 256; off <<= 1) {
        int u = (t >= off) ? sm[t - off] : 0;
        __syncthreads();
        sm[t] += u;
        __syncthreads();
    }
    if (t < SCB) g_part[t] = sm[t] - v;
}

__global__ void k_scan3() {
    __shared__ int sm[256];
    int t = threadIdx.x;
    int i = blockIdx.x * 256 + t;
    int v = (i < NN) ? g_deg[i] : 0;
    sm[t] = v;
    __syncthreads();
#pragma unroll
    for (int off = 1; off < 256; off <<= 1) {
        int u = (t >= off) ? sm[t - off] : 0;
        __syncthreads();
        sm[t] += u;
        __syncthreads();
    }
    int excl = sm[t] - v + g_part[blockIdx.x];
    if (i < NN) { g_off[i] = excl; g_cursor[i] = excl; }
    if (i == NN - 1) g_off[NN] = excl + v;
}

__global__ void k_fill(const int* __restrict__ ei) {
    int i = blockIdx.x * blockDim.x + threadIdx.x;
    if (i >= ETOT) return;
    int s, d;
    if (i < EE) {
        s = edge_src(ei, i);
        d = edge_dst(ei, i);
        if ((unsigned)s >= NN || (unsigned)d >= NN) return;
    } else {
        s = d = i - EE;
    }
    int pos = atomicAdd(&g_cursor[d], 1);
    if ((unsigned)pos < ETOT) g_csr_src[pos] = s;
}

// ---------------- TF32 helpers -------------------------------------------------
__device__ __forceinline__ uint32_t f2tf32(float x) {
    uint32_t r;
    asm("cvt.rna.tf32.f32 %0, %1;" : "=r"(r) : "f"(x));
    return r;
}

__device__ __forceinline__ void mma1688(float* c, const uint32_t* a, const uint32_t* b) {
    asm volatile(
        "mma.sync.aligned.m16n8k8.row.col.f32.tf32.tf32.f32 "
        "{%0,%1,%2,%3}, {%4,%5,%6,%7}, {%8,%9}, {%0,%1,%2,%3};\n"
        : "+f"(c[0]), "+f"(c[1]), "+f"(c[2]), "+f"(c[3])
        : "r"(a[0]), "r"(a[1]), "r"(a[2]), "r"(a[3]), "r"(b[0]), "r"(b[1]));
}

// ---------------- TF32 GEMM (3xTF32) + fused attention dots --------------------
// g_hA = A @ W ; g_es += (A@W).a_s ; g_ed += (A@W).a_d
// 128x128 CTA tile, BK=8, 8 warps (2 m x 4 n), warp tile 64x32, m16n8k8.
__global__ void __launch_bounds__(256, 1)
k_gemm(const float* Aext, const float* __restrict__ B, int M,
       const float* __restrict__ a_s, const float* __restrict__ a_d) {
    const float* A = Aext ? Aext : (const float*)g_hB;
    float* Cout = g_hA;
    const int K = 256, NC = 256;

    __shared__ uint32_t Ah[2][8][132], Al[2][8][132];
    __shared__ uint32_t Bh[2][8][132], Bl[2][8][132];

    const int tid  = threadIdx.x;
    const int wid  = tid >> 5;
    const int lane = tid & 31;
    const int gid  = lane >> 2;      // groupID 0..7
    const int tig  = lane & 3;       // threadID-in-group 0..3
    const int wm   = wid >> 2;       // 0..1 : m-offset 64*wm
    const int wn   = wid & 3;        // 0..3 : n-offset 32*wn
    const int brow = blockIdx.x * 128;
    const int bcol = blockIdx.y * 128;

    // global->smem load mapping
    const int a_row = tid >> 1;          // 0..127
    const int a_k   = (tid & 1) * 4;     // 0 or 4
    const int b_row = tid >> 5;          // 0..7 (k)
    const int b_col = (tid & 31) * 4;    // 0..124 (n)
    const int gr    = brow + a_row;

    float acc[4][4][4];
#pragma unroll
    for (int mf = 0; mf < 4; mf++)
#pragma unroll
        for (int nf = 0; nf < 4; nf++)
#pragma unroll
            for (int c = 0; c < 4; c++) acc[mf][nf][c] = 0.f;

    // prologue: stage tile 0 into buffer 0
    {
        float4 av = make_float4(0.f, 0.f, 0.f, 0.f);
        if (gr < M) av = *(const float4*)&A[(size_t)gr * K + a_k];
        float a4[4] = {av.x, av.y, av.z, av.w};
#pragma unroll
        for (int i = 0; i < 4; i++) {
            uint32_t h = f2tf32(a4[i]);
            Ah[0][a_k + i][a_row] = h;
            Al[0][a_k + i][a_row] = f2tf32(a4[i] - __uint_as_float(h));
        }
        float4 bv = *(const float4*)&B[(size_t)b_row * NC + bcol + b_col];
        float b4[4] = {bv.x, bv.y, bv.z, bv.w};
#pragma unroll
        for (int i = 0; i < 4; i++) {
            uint32_t h = f2tf32(b4[i]);
            Bh[0][b_row][b_col + i] = h;
            Bl[0][b_row][b_col + i] = f2tf32(b4[i] - __uint_as_float(h));
        }
    }
    __syncthreads();

    int buf = 0;
    for (int k0 = 8; k0 <= K; k0 += 8) {
        const bool more = (k0 < K);
        float4 av = make_float4(0.f, 0.f, 0.f, 0.f), bv;
        if (more) {
            if (gr < M) av = *(const float4*)&A[(size_t)gr * K + k0 + a_k];
            bv = *(const float4*)&B[(size_t)(k0 + b_row) * NC + bcol + b_col];
        }

        // fragment loads from smem
        uint32_t ah[4][4], al[4][4], bh[4][2], bl[4][2];
#pragma unroll
        for (int mf = 0; mf < 4; mf++) {
            int m0 = wm * 64 + mf * 16 + gid;
            ah[mf][0] = Ah[buf][tig][m0];
            ah[mf][1] = Ah[buf][tig][m0 + 8];
            ah[mf][2] = Ah[buf][tig + 4][m0];
            ah[mf][3] = Ah[buf][tig + 4][m0 + 8];
            al[mf][0] = Al[buf][tig][m0];
            al[mf][1] = Al[buf][tig][m0 + 8];
            al[mf][2] = Al[buf][tig + 4][m0];
            al[mf][3] = Al[buf][tig + 4][m0 + 8];
        }
#pragma unroll
        for (int nf = 0; nf < 4; nf++) {
            int n0 = wn * 32 + nf * 8 + gid;
            bh[nf][0] = Bh[buf][tig][n0];
            bh[nf][1] = Bh[buf][tig + 4][n0];
            bl[nf][0] = Bl[buf][tig][n0];
            bl[nf][1] = Bl[buf][tig + 4][n0];
        }

        // 3xTF32: D += Ah*Bh + Ah*Bl + Al*Bh
#pragma unroll
        for (int mf = 0; mf < 4; mf++)
#pragma unroll
            for (int nf = 0; nf < 4; nf++) {
                mma1688(acc[mf][nf], ah[mf], bh[nf]);
                mma1688(acc[mf][nf], ah[mf], bl[nf]);
                mma1688(acc[mf][nf], al[mf], bh[nf]);
            }

        if (more) {
            int nb = buf ^ 1;
            float a4[4] = {av.x, av.y, av.z, av.w};
#pragma unroll
            for (int i = 0; i < 4; i++) {
                uint32_t h = f2tf32(a4[i]);
                Ah[nb][a_k + i][a_row] = h;
                Al[nb][a_k + i][a_row] = f2tf32(a4[i] - __uint_as_float(h));
            }
            float b4[4] = {bv.x, bv.y, bv.z, bv.w};
#pragma unroll
            for (int i = 0; i < 4; i++) {
                uint32_t h = f2tf32(b4[i]);
                Bh[nb][b_row][b_col + i] = h;
                Bl[nb][b_row][b_col + i] = f2tf32(b4[i] - __uint_as_float(h));
            }
            __syncthreads();
            buf = nb;
        }
    }

    // epilogue: fused attention dots + C store
    float as0[4], as1[4], ad0[4], ad1[4];
#pragma unroll
    for (int nf = 0; nf < 4; nf++) {
        int c = bcol + wn * 32 + nf * 8 + 2 * tig;
        as0[nf] = a_s[c];     as1[nf] = a_s[c + 1];
        ad0[nf] = a_d[c];     ad1[nf] = a_d[c + 1];
    }
#pragma unroll
    for (int mf = 0; mf < 4; mf++) {
        int r0 = brow + wm * 64 + mf * 16 + gid;
        int r1 = r0 + 8;
        float ps0 = 0.f, pd0 = 0.f, ps1 = 0.f, pd1 = 0.f;
#pragma unroll
        for (int nf = 0; nf < 4; nf++) {
            ps0 = fmaf(acc[mf][nf][0], as0[nf], fmaf(acc[mf][nf][1], as1[nf], ps0));
            pd0 = fmaf(acc[mf][nf][0], ad0[nf], fmaf(acc[mf][nf][1], ad1[nf], pd0));
            ps1 = fmaf(acc[mf][nf][2], as0[nf], fmaf(acc[mf][nf][3], as1[nf], ps1));
            pd1 = fmaf(acc[mf][nf][2], ad0[nf], fmaf(acc[mf][nf][3], ad1[nf], pd1));
        }
        // reduce across tig (lane bits 0..1)
#pragma unroll
        for (int o = 1; o <= 2; o <<= 1) {
            ps0 += __shfl_xor_sync(0xFFFFFFFFu, ps0, o);
            pd0 += __shfl_xor_sync(0xFFFFFFFFu, pd0, o);
            ps1 += __shfl_xor_sync(0xFFFFFFFFu, ps1, o);
            pd1 += __shfl_xor_sync(0xFFFFFFFFu, pd1, o);
        }
#pragma unroll
        for (int nf = 0; nf < 4; nf++) {
            int c = bcol + wn * 32 + nf * 8 + 2 * tig;
            if (r0 < M) {
                float2 v = make_float2(acc[mf][nf][0], acc[mf][nf][1]);
                *(float2*)&Cout[(size_t)r0 * NC + c] = v;
            }
            if (r1 < M) {
                float2 v = make_float2(acc[mf][nf][2], acc[mf][nf][3]);
                *(float2*)&Cout[(size_t)r1 * NC + c] = v;
            }
        }
        if (tig == 0) {
            if (r0 < M) { atomicAdd(&g_es[r0], ps0); atomicAdd(&g_ed[r0], pd0); }
            if (r1 < M) { atomicAdd(&g_es[r1], ps1); atomicAdd(&g_ed[r1], pd1); }
        }
    }
}

// ---------------- aggregation: segment softmax + weighted gather ---------------
// one 256-thread block per dst node; tid == feature dim in pass C.
// If Wc != nullptr: fused classifier + log_softmax.
__global__ void __launch_bounds__(256)
k_aggr(const float* __restrict__ bias,
       const float* __restrict__ Wc, const float* __restrict__ bc,
       float* __restrict__ cls_out) {
    const float* Hin = (const float*)g_hA;
    const int node = blockIdx.x;
    const int tid = threadIdx.x;
    const int beg = g_off[node];
    const int end = g_off[node + 1];
    const float edv = g_ed[node];

    __shared__ float red[8];
    __shared__ float s_m, s_inv;
    __shared__ int   s_src[128];
    __shared__ float s_w[128];

    // pass A: e = leaky_relu(es[src]+ed[dst]); store; segment max
    float m = -1e30f;
    for (int j = beg + tid; j < end; j += 256) {
        float e = g_es[g_csr_src[j]] + edv;
        e = (e > 0.f) ? e : SLOPE * e;
        g_ex[j] = e;
        m = fmaxf(m, e);
    }
#pragma unroll
    for (int o = 16; o; o >>= 1) m = fmaxf(m, __shfl_xor_sync(0xFFFFFFFFu, m, o));
    if ((tid & 31) == 0) red[tid >> 5] = m;
    __syncthreads();
    if (tid < 8) {
        float v = red[tid];
#pragma unroll
        for (int o = 4; o; o >>= 1) v = fmaxf(v, __shfl_xor_sync(0xFFu, v, o));
        if (tid == 0) s_m = v;
    }
    __syncthreads();
    const float mm = s_m;

    // pass B: exp + denominator
    float den = 0.f;
    for (int j = beg + tid; j < end; j += 256) {
        float ex = __expf(g_ex[j] - mm);
        g_ex[j] = ex;
        den += ex;
    }
#pragma unroll
    for (int o = 16; o; o >>= 1) den += __shfl_xor_sync(0xFFFFFFFFu, den, o);
    if ((tid & 31) == 0) red[tid >> 5] = den;
    __syncthreads();
    if (tid < 8) {
        float v = red[tid];
#pragma unroll
        for (int o = 4; o; o >>= 1) v += __shfl_xor_sync(0xFFu, v, o);
        if (tid == 0) s_inv = 1.f / v;
    }
    __syncthreads();
    const float inv = s_inv;

    // pass C: weighted gather (tid == feature dim)
    float acc = 0.f;
    for (int base = beg; base < end; base += 128) {
        int n = min(128, end - base);
        __syncthreads();
        if (tid < n) {
            s_src[tid] = g_csr_src[base + tid];
            s_w[tid]   = g_ex[base + tid];
        }
        __syncthreads();
        for (int k = 0; k < n; k++)
            acc = fmaf(s_w[k], Hin[(size_t)s_src[k] * DD + tid], acc);
    }
    float val = fmaf(acc, inv, bias[tid]);
    val = fmaxf(val, 0.f);   // relu

    if (Wc == nullptr) {
        g_hB[(size_t)node * DD + tid] = val;
        return;
    }

    // fused classifier + log_softmax
    float p0 = val * Wc[2 * tid + 0];
    float p1 = val * Wc[2 * tid + 1];
#pragma unroll
    for (int o = 16; o; o >>= 1) {
        p0 += __shfl_xor_sync(0xFFFFFFFFu, p0, o);
        p1 += __shfl_xor_sync(0xFFFFFFFFu, p1, o);
    }
    __syncthreads();
    if ((tid & 31) == 0) { red[tid >> 5] = p0; }
    __syncthreads();
    float l0 = 0.f, l1 = 0.f;
    if (tid < 8) l0 = red[tid];
    __syncthreads();
    if ((tid & 31) == 0) { red[tid >> 5] = p1; }
    __syncthreads();
    if (tid < 8) {
        l1 = red[tid];
#pragma unroll
        for (int o = 4; o; o >>= 1) {
            l0 += __shfl_xor_sync(0xFFu, l0, o);
            l1 += __shfl_xor_sync(0xFFu, l1, o);
        }
        if (tid == 0) {
            l0 += bc[0]; l1 += bc[1];
            float mx = fmaxf(l0, l1);
            float z0 = l0 - mx, z1 = l1 - mx;
            float lse = logf(expf(z0) + expf(z1));
            cls_out[(size_t)node * 2 + 0] = z0 - lse;
            cls_out[(size_t)node * 2 + 1] = z1 - lse;
        }
    }
}

// ---------------- launch ---------------------------------------------------------
extern "C" void kernel_launch(void* const* d_in, const int* in_sizes, int n_in,
                              void* d_out, int out_size) {
    const float* x   = (const float*)d_in[0];
    const int*   ei  = (const int*)d_in[1];    // int32 OR int64 (device-probed)
    const float* W1  = (const float*)d_in[2];
    const float* a1s = (const float*)d_in[3];
    const float* a1d = (const float*)d_in[4];
    const float* b1  = (const float*)d_in[5];
    const float* W2  = (const float*)d_in[6];
    const float* a2s = (const float*)d_in[7];
    const float* a2d = (const float*)d_in[8];
    const float* b2  = (const float*)d_in[9];
    const float* Wc  = (const float*)d_in[10];
    const float* bc  = (const float*)d_in[11];
    float*       out = (float*)d_out;

    // CSR build
    k_detect<<<1, 1>>>(ei);
    k_init_deg<<<SCB, 256>>>();
    k_hist<<<(EE + 255) / 256, 256>>>(ei);
    k_scan1<<<SCB, 256>>>();
    k_scan2<<<1, 256>>>();
    k_scan3<<<SCB, 256>>>();
    k_fill<<<(ETOT + 255) / 256, 256>>>(ei);

    dim3 ggrid((NN + 127) / 128, DD / 128);   // 391 x 2

    // layer 1
    k_zero_attn<<<SCB, 256>>>();
    k_gemm<<<ggrid, 256>>>(x, W1, NN, a1s, a1d);
    k_aggr<<<NN, 256>>>(b1, nullptr, nullptr, nullptr);

    // layer 2 (+ fused classifier)
    k_zero_attn<<<SCB, 256>>>();
    k_gemm<<<ggrid, 256>>>(nullptr, W2, NN, a2s, a2d);
    k_aggr<<<NN, 256>>>(b2, Wc, bc, out);
}

// round 11
// speedup vs baseline: 1.3537x; 1.1763x over previous
#include <cuda_runtime.h>
#include <cuda_fp16.h>
#include <math.h>
#include <stdint.h>

// Problem constants (fixed shapes per reference)
#define NN 50000
#define EE 800000
#define DD 256
#define CC 2
#define ETOT (EE + NN)   // edges + self loops = 850000
#define SLOPE 0.2f
#define SCB 196          // ceil(NN / 256) scan blocks

// ---------------- scratch (__device__ globals; device-code-only references) --
__device__ __half g_hA[(size_t)NN * DD];  // GEMM output h, fp16 (gather path only)
__device__ float  g_hB[(size_t)NN * DD];  // aggregated/relu'd layer output (fp32)
__device__ float  g_es[NN];
__device__ float  g_ed[NN];
__device__ int    g_deg[NN];
__device__ int    g_off[NN + 1];
__device__ int    g_cursor[NN];
__device__ int    g_csr_src[ETOT];
__device__ float  g_ex[ETOT];
__device__ int    g_part[256];            // scan partials (SCB used)
__device__ int    g_is64;                 // edge_index dtype flag

// ---------------- edge dtype probe ------------------------------------------
__global__ void k_detect(const int* __restrict__ ei) {
    int all0 = 1;
#pragma unroll
    for (int i = 1; i < 128; i += 2) all0 &= (ei[i] == 0);
    g_is64 = all0;
}

__device__ __forceinline__ int edge_src(const int* __restrict__ ei, int i) {
    return g_is64 ? ei[2 * i] : ei[i];
}
__device__ __forceinline__ int edge_dst(const int* __restrict__ ei, int i) {
    return g_is64 ? ei[2 * EE + 2 * i] : ei[EE + i];
}

// ---------------- CSR build ---------------------------------------------------
__global__ void k_init_deg() {
    int i = blockIdx.x * blockDim.x + threadIdx.x;
    if (i < NN) g_deg[i] = 1;   // self loop
}

__global__ void k_zero_attn() {
    int i = blockIdx.x * blockDim.x + threadIdx.x;
    if (i < NN) { g_es[i] = 0.f; g_ed[i] = 0.f; }
}

__global__ void k_hist(const int* __restrict__ ei) {
    int i = blockIdx.x * blockDim.x + threadIdx.x;
    if (i < EE) {
        int d = edge_dst(ei, i);
        if ((unsigned)d < NN) atomicAdd(&g_deg[d], 1);
    }
}

__global__ void k_scan1() {
    __shared__ int red[8];
    int i = blockIdx.x * 256 + threadIdx.x;
    int v = (i < NN) ? g_deg[i] : 0;
    int s = v;
#pragma unroll
    for (int o = 16; o; o >>= 1) s += __shfl_xor_sync(0xFFFFFFFFu, s, o);
    if ((threadIdx.x & 31) == 0) red[threadIdx.x >> 5] = s;
    __syncthreads();
    if (threadIdx.x < 8) {
        int t = red[threadIdx.x];
#pragma unroll
        for (int o = 4; o; o >>= 1) t += __shfl_xor_sync(0xFFu, t, o);
        if (threadIdx.x == 0) g_part[blockIdx.x] = t;
    }
}

__global__ void k_scan2() {
    __shared__ int sm[256];
    int t = threadIdx.x;
    int v = (t < SCB) ? g_part[t] : 0;
    sm[t] = v;
    __syncthreads();
#pragma unroll
    for (int off = 1; off < 256; off <<= 1) {
        int u = (t >= off) ? sm[t - off] : 0;
        __syncthreads();
        sm[t] += u;
        __syncthreads();
    }
    if (t < SCB) g_part[t] = sm[t] - v;
}

__global__ void k_scan3() {
    __shared__ int sm[256];
    int t = threadIdx.x;
    int i = blockIdx.x * 256 + t;
    int v = (i < NN) ? g_deg[i] : 0;
    sm[t] = v;
    __syncthreads();
#pragma unroll
    for (int off = 1; off < 256; off <<= 1) {
        int u = (t >= off) ? sm[t - off] : 0;
        __syncthreads();
        sm[t] += u;
        __syncthreads();
    }
    int excl = sm[t] - v + g_part[blockIdx.x];
    if (i < NN) { g_off[i] = excl; g_cursor[i] = excl; }
    if (i == NN - 1) g_off[NN] = excl + v;
}

__global__ void k_fill(const int* __restrict__ ei) {
    int i = blockIdx.x * blockDim.x + threadIdx.x;
    if (i >= ETOT) return;
    int s, d;
    if (i < EE) {
        s = edge_src(ei, i);
        d = edge_dst(ei, i);
        if ((unsigned)s >= NN || (unsigned)d >= NN) return;
    } else {
        s = d = i - EE;
    }
    int pos = atomicAdd(&g_cursor[d], 1);
    if ((unsigned)pos < ETOT) g_csr_src[pos] = s;
}

// ---------------- TF32 helpers -------------------------------------------------
__device__ __forceinline__ uint32_t f2tf32(float x) {
    uint32_t r;
    asm("cvt.rna.tf32.f32 %0, %1;" : "=r"(r) : "f"(x));
    return r;
}

__device__ __forceinline__ void mma1688(float* c, const uint32_t* a, const uint32_t* b) {
    asm volatile(
        "mma.sync.aligned.m16n8k8.row.col.f32.tf32.tf32.f32 "
        "{%0,%1,%2,%3}, {%4,%5,%6,%7}, {%8,%9}, {%0,%1,%2,%3};\n"
        : "+f"(c[0]), "+f"(c[1]), "+f"(c[2]), "+f"(c[3])
        : "r"(a[0]), "r"(a[1]), "r"(a[2]), "r"(a[3]), "r"(b[0]), "r"(b[1]));
}

// ---------------- TF32 GEMM (3xTF32) + fused attention dots --------------------
// g_hA(fp16) = A @ W ; g_es += h.a_s ; g_ed += h.a_d    (dots at fp32)
// 128x128 CTA tile, BK=16, 8 warps (2m x 4n), warp tile 64x32, m16n8k8.
__global__ void __launch_bounds__(256)
k_gemm(const float* Aext, const float* __restrict__ B, int M,
       const float* __restrict__ a_s, const float* __restrict__ a_d) {
    const float* A = Aext ? Aext : (const float*)g_hB;
    __half* Cout = g_hA;
    const int K = 256, NC = 256;

    __shared__ uint32_t Ah[16][132], Al[16][132];
    __shared__ uint32_t Bh[16][132], Bl[16][132];

    const int tid  = threadIdx.x;
    const int wid  = tid >> 5;
    const int lane = tid & 31;
    const int gid  = lane >> 2;      // 0..7
    const int tig  = lane & 3;       // 0..3
    const int wm   = wid >> 2;       // 0..1
    const int wn   = wid & 3;        // 0..3
    const int brow = blockIdx.x * 128;
    const int bcol = blockIdx.y * 128;

    const int a_row = tid >> 1;          // 0..127
    const int a_k   = (tid & 1) * 8;     // 0 or 8
    const int b_row = tid >> 4;          // 0..15 (k)
    const int b_col = (tid & 15) * 8;    // 0..120 (n)
    const int gr    = brow + a_row;

    float acc[4][4][4];
#pragma unroll
    for (int mf = 0; mf < 4; mf++)
#pragma unroll
        for (int nf = 0; nf < 4; nf++)
#pragma unroll
            for (int c = 0; c < 4; c++) acc[mf][nf][c] = 0.f;

    float sa[8], sb[8];
    // prologue: load tile k0=0, convert, store
    {
        float4 av0 = make_float4(0.f, 0.f, 0.f, 0.f), av1 = av0;
        if (gr < M) {
            av0 = *(const float4*)&A[(size_t)gr * K + a_k];
            av1 = *(const float4*)&A[(size_t)gr * K + a_k + 4];
        }
        float4 bv0 = *(const float4*)&B[(size_t)b_row * NC + bcol + b_col];
        float4 bv1 = *(const float4*)&B[(size_t)b_row * NC + bcol + b_col + 4];
        sa[0]=av0.x; sa[1]=av0.y; sa[2]=av0.z; sa[3]=av0.w;
        sa[4]=av1.x; sa[5]=av1.y; sa[6]=av1.z; sa[7]=av1.w;
        sb[0]=bv0.x; sb[1]=bv0.y; sb[2]=bv0.z; sb[3]=bv0.w;
        sb[4]=bv1.x; sb[5]=bv1.y; sb[6]=bv1.z; sb[7]=bv1.w;
#pragma unroll
        for (int i = 0; i < 8; i++) {
            uint32_t h = f2tf32(sa[i]);
            Ah[a_k + i][a_row] = h;
            Al[a_k + i][a_row] = f2tf32(sa[i] - __uint_as_float(h));
            uint32_t hb = f2tf32(sb[i]);
            Bh[b_row][b_col + i] = hb;
            Bl[b_row][b_col + i] = f2tf32(sb[i] - __uint_as_float(hb));
        }
    }
    __syncthreads();

    for (int k0 = 16; k0 <= K; k0 += 16) {
        const bool more = (k0 < K);
        if (more) {   // prefetch next tile into registers
            float4 av0 = make_float4(0.f, 0.f, 0.f, 0.f), av1 = av0;
            if (gr < M) {
                av0 = *(const float4*)&A[(size_t)gr * K + k0 + a_k];
                av1 = *(const float4*)&A[(size_t)gr * K + k0 + a_k + 4];
            }
            float4 bv0 = *(const float4*)&B[(size_t)(k0 + b_row) * NC + bcol + b_col];
            float4 bv1 = *(const float4*)&B[(size_t)(k0 + b_row) * NC + bcol + b_col + 4];
            sa[0]=av0.x; sa[1]=av0.y; sa[2]=av0.z; sa[3]=av0.w;
            sa[4]=av1.x; sa[5]=av1.y; sa[6]=av1.z; sa[7]=av1.w;
            sb[0]=bv0.x; sb[1]=bv0.y; sb[2]=bv0.z; sb[3]=bv0.w;
            sb[4]=bv1.x; sb[5]=bv1.y; sb[6]=bv1.z; sb[7]=bv1.w;
        }

#pragma unroll
        for (int kc = 0; kc < 2; kc++) {
            const int kb = kc * 8;
            uint32_t ah[4][4], al[4][4], bh[4][2], bl[4][2];
#pragma unroll
            for (int mf = 0; mf < 4; mf++) {
                int m0 = wm * 64 + mf * 16 + gid;
                ah[mf][0] = Ah[kb + tig][m0];
                ah[mf][1] = Ah[kb + tig][m0 + 8];
                ah[mf][2] = Ah[kb + tig + 4][m0];
                ah[mf][3] = Ah[kb + tig + 4][m0 + 8];
                al[mf][0] = Al[kb + tig][m0];
                al[mf][1] = Al[kb + tig][m0 + 8];
                al[mf][2] = Al[kb + tig + 4][m0];
                al[mf][3] = Al[kb + tig + 4][m0 + 8];
            }
#pragma unroll
            for (int nf = 0; nf < 4; nf++) {
                int n0 = wn * 32 + nf * 8 + gid;
                bh[nf][0] = Bh[kb + tig][n0];
                bh[nf][1] = Bh[kb + tig + 4][n0];
                bl[nf][0] = Bl[kb + tig][n0];
                bl[nf][1] = Bl[kb + tig + 4][n0];
            }
#pragma unroll
            for (int mf = 0; mf < 4; mf++)
#pragma unroll
                for (int nf = 0; nf < 4; nf++) {
                    mma1688(acc[mf][nf], ah[mf], bh[nf]);
                    mma1688(acc[mf][nf], ah[mf], bl[nf]);
                    mma1688(acc[mf][nf], al[mf], bh[nf]);
                }
        }

        if (more) {
            __syncthreads();   // all fragment reads of current tile done
#pragma unroll
            for (int i = 0; i < 8; i++) {
                uint32_t h = f2tf32(sa[i]);
                Ah[a_k + i][a_row] = h;
                Al[a_k + i][a_row] = f2tf32(sa[i] - __uint_as_float(h));
                uint32_t hb = f2tf32(sb[i]);
                Bh[b_row][b_col + i] = hb;
                Bl[b_row][b_col + i] = f2tf32(sb[i] - __uint_as_float(hb));
            }
            __syncthreads();
        }
    }

    // epilogue: fused attention dots (fp32) + fp16 C store
    float as0[4], as1[4], ad0[4], ad1[4];
#pragma unroll
    for (int nf = 0; nf < 4; nf++) {
        int c = bcol + wn * 32 + nf * 8 + 2 * tig;
        as0[nf] = a_s[c];     as1[nf] = a_s[c + 1];
        ad0[nf] = a_d[c];     ad1[nf] = a_d[c + 1];
    }
#pragma unroll
    for (int mf = 0; mf < 4; mf++) {
        int r0 = brow + wm * 64 + mf * 16 + gid;
        int r1 = r0 + 8;
        float ps0 = 0.f, pd0 = 0.f, ps1 = 0.f, pd1 = 0.f;
#pragma unroll
        for (int nf = 0; nf < 4; nf++) {
            ps0 = fmaf(acc[mf][nf][0], as0[nf], fmaf(acc[mf][nf][1], as1[nf], ps0));
            pd0 = fmaf(acc[mf][nf][0], ad0[nf], fmaf(acc[mf][nf][1], ad1[nf], pd0));
            ps1 = fmaf(acc[mf][nf][2], as0[nf], fmaf(acc[mf][nf][3], as1[nf], ps1));
            pd1 = fmaf(acc[mf][nf][2], ad0[nf], fmaf(acc[mf][nf][3], ad1[nf], pd1));
        }
#pragma unroll
        for (int o = 1; o <= 2; o <<= 1) {
            ps0 += __shfl_xor_sync(0xFFFFFFFFu, ps0, o);
            pd0 += __shfl_xor_sync(0xFFFFFFFFu, pd0, o);
            ps1 += __shfl_xor_sync(0xFFFFFFFFu, ps1, o);
            pd1 += __shfl_xor_sync(0xFFFFFFFFu, pd1, o);
        }
#pragma unroll
        for (int nf = 0; nf < 4; nf++) {
            int c = bcol + wn * 32 + nf * 8 + 2 * tig;
            if (r0 < M)
                ((__half2*)Cout)[((size_t)r0 * NC + c) >> 1] =
                    __floats2half2_rn(acc[mf][nf][0], acc[mf][nf][1]);
            if (r1 < M)
                ((__half2*)Cout)[((size_t)r1 * NC + c) >> 1] =
                    __floats2half2_rn(acc[mf][nf][2], acc[mf][nf][3]);
        }
        if (tig == 0) {
            if (r0 < M) { atomicAdd(&g_es[r0], ps0); atomicAdd(&g_ed[r0], pd0); }
            if (r1 < M) { atomicAdd(&g_es[r1], ps1); atomicAdd(&g_ed[r1], pd1); }
        }
    }
}

// ---------------- aggregation: online segment softmax + fp16 gather -------------
// 128 threads per block; thread t owns the half2 feature pair (2t, 2t+1).
// If Wc != nullptr: fused classifier + log_softmax.
__global__ void __launch_bounds__(128)
k_aggr(const float* __restrict__ bias,
       const float* __restrict__ Wc, const float* __restrict__ bc,
       float* __restrict__ cls_out) {
    const __half2* Hin = (const __half2*)g_hA;
    const int node = blockIdx.x;
    const int tid = threadIdx.x;      // 0..127
    const int lane = tid & 31;
    const int beg = g_off[node];
    const int end = g_off[node + 1];
    const float edv = g_ed[node];

    __shared__ float redm[4], redd[4];
    __shared__ float s_m, s_inv;
    __shared__ int   s_src[128];
    __shared__ float s_w[128];

    // pass A: online softmax (max + denominator in one sweep); store raw e
    float m = -1e30f, d = 0.f;
    for (int j = beg + tid; j < end; j += 128) {
        float e = g_es[g_csr_src[j]] + edv;
        e = (e > 0.f) ? e : SLOPE * e;
        g_ex[j] = e;
        if (e > m) { d = fmaf(d, __expf(m - e), 1.f); m = e; }
        else       { d += __expf(e - m); }
    }
#pragma unroll
    for (int o = 16; o; o >>= 1) {
        float om = __shfl_xor_sync(0xFFFFFFFFu, m, o);
        float od = __shfl_xor_sync(0xFFFFFFFFu, d, o);
        float nm = fmaxf(m, om);
        d = d * __expf(m - nm) + od * __expf(om - nm);
        m = nm;
    }
    if (lane == 0) { redm[tid >> 5] = m; redd[tid >> 5] = d; }
    __syncthreads();
    if (tid < 4) {
        float vm = redm[tid], vd = redd[tid];
#pragma unroll
        for (int o = 2; o; o >>= 1) {
            float om = __shfl_xor_sync(0xFu, vm, o);
            float od = __shfl_xor_sync(0xFu, vd, o);
            float nm = fmaxf(vm, om);
            vd = vd * __expf(vm - nm) + od * __expf(om - nm);
            vm = nm;
        }
        if (tid == 0) { s_m = vm; s_inv = 1.f / vd; }
    }
    __syncthreads();
    const float mm  = s_m;
    const float inv = s_inv;

    // pass C: weighted fp16 gather (thread = one half2 feature pair)
    float ax = 0.f, ay = 0.f;
    for (int base = beg; base < end; base += 128) {
        int n = min(128, end - base);
        __syncthreads();
        if (tid < n) {
            s_src[tid] = g_csr_src[base + tid];
            s_w[tid]   = __expf(g_ex[base + tid] - mm);
        }
        __syncthreads();
        for (int k = 0; k < n; k++) {
            float w = s_w[k];
            float2 f = __half22float2(Hin[(size_t)s_src[k] * 128 + tid]);
            ax = fmaf(w, f.x, ax);
            ay = fmaf(w, f.y, ay);
        }
    }
    float v0 = fmaxf(fmaf(ax, inv, bias[2 * tid]), 0.f);
    float v1 = fmaxf(fmaf(ay, inv, bias[2 * tid + 1]), 0.f);

    if (Wc == nullptr) {
        ((float2*)g_hB)[(size_t)node * 128 + tid] = make_float2(v0, v1);
        return;
    }

    // fused classifier + log_softmax (Wc is [256,2] row-major)
    float p0 = v0 * Wc[4 * tid + 0] + v1 * Wc[4 * tid + 2];
    float p1 = v0 * Wc[4 * tid + 1] + v1 * Wc[4 * tid + 3];
#pragma unroll
    for (int o = 16; o; o >>= 1) {
        p0 += __shfl_xor_sync(0xFFFFFFFFu, p0, o);
        p1 += __shfl_xor_sync(0xFFFFFFFFu, p1, o);
    }
    __syncthreads();   // red arrays reused
    if (lane == 0) { redm[tid >> 5] = p0; redd[tid >> 5] = p1; }
    __syncthreads();
    if (tid < 4) {
        float l0 = redm[tid], l1 = redd[tid];
#pragma unroll
        for (int o = 2; o; o >>= 1) {
            l0 += __shfl_xor_sync(0xFu, l0, o);
            l1 += __shfl_xor_sync(0xFu, l1, o);
        }
        if (tid == 0) {
            l0 += bc[0]; l1 += bc[1];
            float mx = fmaxf(l0, l1);
            float z0 = l0 - mx, z1 = l1 - mx;
            float lse = logf(expf(z0) + expf(z1));
            cls_out[(size_t)node * 2 + 0] = z0 - lse;
            cls_out[(size_t)node * 2 + 1] = z1 - lse;
        }
    }
}

// ---------------- launch ---------------------------------------------------------
extern "C" void kernel_launch(void* const* d_in, const int* in_sizes, int n_in,
                              void* d_out, int out_size) {
    const float* x   = (const float*)d_in[0];
    const int*   ei  = (const int*)d_in[1];    // int32 OR int64 (device-probed)
    const float* W1  = (const float*)d_in[2];
    const float* a1s = (const float*)d_in[3];
    const float* a1d = (const float*)d_in[4];
    const float* b1  = (const float*)d_in[5];
    const float* W2  = (const float*)d_in[6];
    const float* a2s = (const float*)d_in[7];
    const float* a2d = (const float*)d_in[8];
    const float* b2  = (const float*)d_in[9];
    const float* Wc  = (const float*)d_in[10];
    const float* bc  = (const float*)d_in[11];
    float*       out = (float*)d_out;

    // CSR build
    k_detect<<<1, 1>>>(ei);
    k_init_deg<<<SCB, 256>>>();
    k_hist<<<(EE + 255) / 256, 256>>>(ei);
    k_scan1<<<SCB, 256>>>();
    k_scan2<<<1, 256>>>();
    k_scan3<<<SCB, 256>>>();
    k_fill<<<(ETOT + 255) / 256, 256>>>(ei);

    dim3 ggrid((NN + 127) / 128, DD / 128);   // 391 x 2

    // layer 1
    k_zero_attn<<<SCB, 256>>>();
    k_gemm<<<ggrid, 256>>>(x, W1, NN, a1s, a1d);
    k_aggr<<<NN, 128>>>(b1, nullptr, nullptr, nullptr);

    // layer 2 (+ fused classifier)
    k_zero_attn<<<SCB, 256>>>();
    k_gemm<<<ggrid, 256>>>(nullptr, W2, NN, a2s, a2d);
    k_aggr<<<NN, 128>>>(b2, Wc, bc, out);
}